// round 2
// baseline (speedup 1.0000x reference)
#include <cuda_runtime.h>
#include <cstdint>

#define D     16384
#define BATCH 8
#define H0    4096

#define TILE_J  512
#define THREADS 128
#define KCH     256

// Scratch (allocation-free rule: __device__ globals)
__device__ float              g_acc[BATCH * D];
__device__ unsigned long long g_rho2[D * BATCH];   // (rho, rho) packed f32x2, layout [k][b]

__device__ __forceinline__ unsigned long long ffma2(unsigned long long a,
                                                    unsigned long long b,
                                                    unsigned long long c) {
    unsigned long long d;
    asm("fma.rn.f32x2 %0, %1, %2, %3;" : "=l"(d) : "l"(a), "l"(b), "l"(c));
    return d;
}

__device__ __forceinline__ float sigmoid4(float x) {
    return 1.0f / (1.0f + expf(-4.0f * (x - 0.5f)));
}

// ---------------------------------------------------------------------------
// Kernel 1: zero the accumulator, build duplicated-pair rho table [k][b]
// ---------------------------------------------------------------------------
__global__ void prep_kernel(const float* __restrict__ s) {
    int idx = blockIdx.x * blockDim.x + threadIdx.x;
    if (idx < BATCH * D) g_acc[idx] = 0.0f;
    if (idx < D) {
#pragma unroll
        for (int b = 0; b < BATCH; b++) {
            float r = sigmoid4(s[b * D + idx]);
            float2 p = make_float2(r, r);
            g_rho2[idx * BATCH + b] = *reinterpret_cast<unsigned long long*>(&p);
        }
    }
}

// ---------------------------------------------------------------------------
// Kernel 2: split-K block-sparse GEMV  acc[b][j] += sum_k rho[b][k] * W[k][j]
// Only the 6 nonzero 4096x4096 blocks of W are touched (402 MB, not 1 GB).
// gridDim = (32 column tiles, 32 virtual-k chunks of 256)
// ---------------------------------------------------------------------------
__global__ __launch_bounds__(THREADS)
void gemv_kernel(const float* __restrict__ W) {
    __shared__ unsigned long long srho[KCH * BATCH];   // 16 KB

    const int jt  = blockIdx.x;         // 0..31, 512 columns each
    const int jb  = jt >> 3;            // column block 0..3
    const int vk0 = blockIdx.y * KCH;   // virtual k offset within this block's k-range
    const int nk  = (jb == 0 || jb == 3) ? 4096 : 8192;
    if (vk0 >= nk) return;

    // Map virtual k to real k (neighbor blocks of jb). Chunks never straddle
    // the 4096 boundary, so the KCH-range is contiguous in real k.
    int kbase;
    if      (jb == 0) kbase = 4096 + vk0;
    else if (jb == 1) kbase = (vk0 < 4096) ? vk0        : vk0 + 4096;  // blk0 | blk2
    else if (jb == 2) kbase = (vk0 < 4096) ? vk0 + 4096 : vk0 + 8192;  // blk1 | blk3
    else              kbase = 8192 + vk0;                              // blk2

    // Stage this chunk's duplicated rho pairs into smem (from L2-resident table)
    {
        const float4* src = reinterpret_cast<const float4*>(g_rho2 + (size_t)kbase * BATCH);
        float4*       dst = reinterpret_cast<float4*>(srho);
#pragma unroll
        for (int i = threadIdx.x; i < (KCH * BATCH) / 2; i += THREADS)
            dst[i] = src[i];
    }
    __syncthreads();

    const int j0 = jt * TILE_J + threadIdx.x * 4;     // 4 consecutive columns/thread
    const float* Wp = W + (size_t)kbase * D + j0;     // 16B aligned

    unsigned long long acc[BATCH][2];
#pragma unroll
    for (int b = 0; b < BATCH; b++) { acc[b][0] = 0ull; acc[b][1] = 0ull; }

#pragma unroll 4
    for (int kk = 0; kk < KCH; kk++) {
        ulonglong2 w = *reinterpret_cast<const ulonglong2*>(Wp);   // LDG.128: W[k][j0..j0+3]
        Wp += D;
        const ulonglong2* r2 = reinterpret_cast<const ulonglong2*>(srho + kk * BATCH);
#pragma unroll
        for (int h = 0; h < 4; h++) {
            ulonglong2 rp = r2[h];                                 // LDS.128: rho pairs b=2h,2h+1
            acc[2*h    ][0] = ffma2(w.x, rp.x, acc[2*h    ][0]);
            acc[2*h    ][1] = ffma2(w.y, rp.x, acc[2*h    ][1]);
            acc[2*h + 1][0] = ffma2(w.x, rp.y, acc[2*h + 1][0]);
            acc[2*h + 1][1] = ffma2(w.y, rp.y, acc[2*h + 1][1]);
        }
    }

    // Combine split-K partials
#pragma unroll
    for (int b = 0; b < BATCH; b++) {
#pragma unroll
        for (int p = 0; p < 2; p++) {
            float2 f = *reinterpret_cast<float2*>(&acc[b][p]);
            atomicAdd(&g_acc[b * D + j0 + 2 * p    ], f.x);
            atomicAdd(&g_acc[b * D + j0 + 2 * p + 1], f.y);
        }
    }
}

// ---------------------------------------------------------------------------
// Kernel 3: epilogue  out = (acc + bias + [Ux|0]) * rho'(s)
// ---------------------------------------------------------------------------
__global__ void epi_kernel(const float* __restrict__ Ux,
                           const float* __restrict__ s,
                           const float* __restrict__ bias,
                           float* __restrict__ out) {
    int idx = blockIdx.x * blockDim.x + threadIdx.x;
    if (idx >= BATCH * D) return;
    int b = idx >> 14;          // idx / 16384
    int j = idx & (D - 1);
    float r  = sigmoid4(s[idx]);
    float rd = 4.0f * r * (1.0f - r);
    float v  = g_acc[idx] + bias[j];
    if (j < H0) v += Ux[b * H0 + j];
    out[idx] = v * rd;
}

// ---------------------------------------------------------------------------
extern "C" void kernel_launch(void* const* d_in, const int* in_sizes, int n_in,
                              void* d_out, int out_size) {
    // Identify inputs by element count (all distinct): Ux 32768, s 131072,
    // W 268435456, b 16384.
    const float *Ux = nullptr, *s = nullptr, *W = nullptr, *bias = nullptr;
    for (int i = 0; i < n_in; i++) {
        switch (in_sizes[i]) {
            case 32768:     Ux   = (const float*)d_in[i]; break;
            case 131072:    s    = (const float*)d_in[i]; break;
            case 268435456: W    = (const float*)d_in[i]; break;
            case 16384:     bias = (const float*)d_in[i]; break;
            default: break;
        }
    }

    prep_kernel<<<(BATCH * D + 255) / 256, 256>>>(s);
    gemv_kernel<<<dim3(D / TILE_J, 8192 / KCH), THREADS>>>(W);
    epi_kernel<<<(BATCH * D + 255) / 256, 256>>>(Ux, s, bias, (float*)d_out);
}

// round 3
// speedup vs baseline: 1.1102x; 1.1102x over previous
#include <cuda_runtime.h>
#include <cstdint>

#define D      16384
#define BATCH  8
#define H0     4096

#define TK      256          // k-rows per CTA tile
#define TJ      256          // j-cols per CTA tile
#define SK      32           // sub-tile rows
#define NSUB    (TK / SK)    // 8
#define THREADS 256

#define ROWB    1040                   // (256 + 4 pad) floats * 4B
#define STAGE_B (SK * ROWB)            // 33280 B per W stage
#define OFF_W0  0
#define OFF_W1  STAGE_B
#define OFF_RR0 (2 * STAGE_B)          // 66560: rho_R dup chunk stage 0 (2KB)
#define OFF_RR1 (OFF_RR0 + 2048)       // 68608: stage 1
#define OFF_RC  (OFF_RR1 + 2048)       // 70656: rho_C pairs (8KB)
#define OFF_TS  (OFF_RC + 8192)        // 78848: T reduction stage (8KB)
#define SMEM_TOTAL (OFF_TS + 8192)     // 87040 B

// Scratch (__device__ globals: allocation-free rule)
__device__ float              g_acc[BATCH * D];
__device__ unsigned long long g_rho2[(size_t)D * BATCH];        // (r,r) dup pairs, [k][b]
__device__ unsigned long long g_rhoc[(size_t)(D / 2) * BATCH];  // (r_2j,r_2j+1) pairs, [j2][b]

__device__ __forceinline__ unsigned long long ffma2(unsigned long long a,
                                                    unsigned long long b,
                                                    unsigned long long c) {
    unsigned long long d;
    asm("fma.rn.f32x2 %0, %1, %2, %3;" : "=l"(d) : "l"(a), "l"(b), "l"(c));
    return d;
}

__device__ __forceinline__ float sigmoid4(float x) {
    return 1.0f / (1.0f + expf(-4.0f * (x - 0.5f)));
}

__device__ __forceinline__ void cpa16(void* smem_dst, const void* gmem_src) {
    uint32_t sa = (uint32_t)__cvta_generic_to_shared(smem_dst);
    asm volatile("cp.async.cg.shared.global [%0], [%1], 16;\n" :: "r"(sa), "l"(gmem_src));
}

// ---------------------------------------------------------------------------
// Kernel 1: zero acc + build rho tables (coalesced consecutive-u64 writes)
// grid = 512 x 256 == BATCH*D threads exactly
// ---------------------------------------------------------------------------
__global__ void prep_kernel(const float* __restrict__ s) {
    int idx = blockIdx.x * blockDim.x + threadIdx.x;   // 0..131071
    g_acc[idx] = 0.0f;
    {
        int k = idx >> 3, b = idx & 7;
        float r = sigmoid4(s[b * D + k]);
        float2 p = make_float2(r, r);
        g_rho2[idx] = *reinterpret_cast<unsigned long long*>(&p);
    }
    if (idx < (D / 2) * BATCH) {
        int j2 = idx >> 3, b = idx & 7;
        float r0 = sigmoid4(s[b * D + 2 * j2]);
        float r1 = sigmoid4(s[b * D + 2 * j2 + 1]);
        float2 p = make_float2(r0, r1);
        g_rhoc[idx] = *reinterpret_cast<unsigned long long*>(&p);
    }
}

// ---------------------------------------------------------------------------
// Kernel 2: symmetric block-tridiag matmul. Each CTA reads one 256x256 tile
// of an UPPER block B_{i,i+1} once and produces BOTH
//   F: out[C] += rho[R] @ B      (column direction)
//   T: out[R] += rho[C] @ B^T    (row-reduction direction)
// DRAM traffic: 3 blocks = 201 MB (half of the 6-block read).
// ---------------------------------------------------------------------------
__global__ __launch_bounds__(THREADS, 2)
void mm_kernel(const float* __restrict__ W) {
    extern __shared__ char smem[];
    const int t = threadIdx.x;
    const int l = t & 31;
    const int w = t >> 5;

    const int cta  = blockIdx.x;            // 0..767
    const int b3   = cta >> 8;              // upper block 0..2
    const int rem  = cta & 255;
    const int it   = rem >> 4;              // k-tile 0..15
    const int jt   = rem & 15;              // j-tile 0..15
    const int row0 = b3 * 4096 + it * TK;
    const int col0 = (b3 + 1) * 4096 + jt * TJ;

    // --- loaders -----------------------------------------------------------
    auto load_sub = [&](int s, int stg) {
        char* dst = smem + (stg ? OFF_W1 : OFF_W0);
        const float* src = W + (size_t)(row0 + s * SK) * D + col0;
#pragma unroll
        for (int i = 0; i < 8; i++) {
            int idx = t + THREADS * i;      // 0..2047
            int r  = idx >> 6;              // row 0..31
            int c4 = idx & 63;              // float4 col
            cpa16(dst + r * ROWB + c4 * 16, src + (size_t)r * D + c4 * 4);
        }
        if (t < 128) {                      // rho_R dup chunk: 2KB
            char* rdst = smem + (stg ? OFF_RR1 : OFF_RR0);
            const char* rsrc = (const char*)g_rho2 + (size_t)(row0 + s * SK) * 64;
            cpa16(rdst + t * 16, rsrc + t * 16);
        }
    };

    // prologue: stage 0 + rho_C (8KB, once)
    load_sub(0, 0);
    {
        const char* csrc = (const char*)g_rhoc + (size_t)(col0 / 2) * 64;
#pragma unroll
        for (int i = 0; i < 2; i++) {
            int f = t + THREADS * i;        // 0..511
            cpa16(smem + OFF_RC + f * 16, csrc + f * 16);
        }
    }
    asm volatile("cp.async.commit_group;\n");

    // F accumulators: thread owns cols j4*4..+3, k-subrange kg (8 rows/sub-tile)
    const int j4 = t & 63;
    const int kg = t >> 6;
    unsigned long long accF[8][2];
#pragma unroll
    for (int b = 0; b < 8; b++) { accF[b][0] = 0ull; accF[b][1] = 0ull; }

    int stg = 0;
    for (int s = 0; s < NSUB; s++) {
        if (s + 1 < NSUB) {
            load_sub(s + 1, stg ^ 1);
            asm volatile("cp.async.commit_group;\n");
            asm volatile("cp.async.wait_group 1;\n");
        } else {
            asm volatile("cp.async.wait_group 0;\n");
        }
        __syncthreads();

        const char* wbuf = smem + (stg ? OFF_W1 : OFF_W0);
        const char* rr   = smem + (stg ? OFF_RR1 : OFF_RR0);

        // ---- Phase F: out_cols += rho_rows * W ----------------------------
        {
            const char* wp = wbuf + (kg * 8) * ROWB + j4 * 16;
            const char* rp = rr + (kg * 8) * 64;
#pragma unroll
            for (int kk = 0; kk < 8; kk++) {
                ulonglong2 w4 = *(const ulonglong2*)wp;  wp += ROWB;
                const ulonglong2* dp = (const ulonglong2*)rp;  rp += 64;
#pragma unroll
                for (int hb = 0; hb < 4; hb++) {
                    ulonglong2 d = dp[hb];               // dup pairs b=2hb, 2hb+1
                    accF[2*hb  ][0] = ffma2(w4.x, d.x, accF[2*hb  ][0]);
                    accF[2*hb  ][1] = ffma2(w4.y, d.x, accF[2*hb  ][1]);
                    accF[2*hb+1][0] = ffma2(w4.x, d.y, accF[2*hb+1][0]);
                    accF[2*hb+1][1] = ffma2(w4.y, d.y, accF[2*hb+1][1]);
                }
            }
        }

        // ---- Phase T: out_rows += W * rho_cols ----------------------------
        {
            unsigned long long accT[8];
#pragma unroll
            for (int b = 0; b < 8; b++) accT[b] = 0ull;

            const char* wp = wbuf + l * ROWB + w * 128;   // row l, cols w*32..
            const char* rc = smem + OFF_RC + (w * 16) * 64;
#pragma unroll
            for (int st = 0; st < 8; st++) {
                ulonglong2 w4 = *(const ulonglong2*)(wp + st * 16);
                const ulonglong2* r0 = (const ulonglong2*)(rc + (st * 2    ) * 64);
                const ulonglong2* r1 = (const ulonglong2*)(rc + (st * 2 + 1) * 64);
#pragma unroll
                for (int hb = 0; hb < 4; hb++) {
                    ulonglong2 p0 = r0[hb];
                    ulonglong2 p1 = r1[hb];
                    accT[2*hb  ] = ffma2(w4.x, p0.x, accT[2*hb  ]);
                    accT[2*hb  ] = ffma2(w4.y, p1.x, accT[2*hb  ]);
                    accT[2*hb+1] = ffma2(w4.x, p0.y, accT[2*hb+1]);
                    accT[2*hb+1] = ffma2(w4.y, p1.y, accT[2*hb+1]);
                }
            }
            // horizontal sum + stage [q=w][kt=l][b]
            float* ts = (float*)(smem + OFF_TS);
#pragma unroll
            for (int b = 0; b < 8; b++) {
                float2 v = *reinterpret_cast<float2*>(&accT[b]);
                ts[t * 8 + b] = v.x + v.y;
            }
        }
        __syncthreads();

        // ---- T reduction over 8 q-groups + atomic flush -------------------
        {
            const float* ts = (const float*)(smem + OFF_TS);
            int kt = t >> 3, b = t & 7;
            float sum = 0.0f;
#pragma unroll
            for (int q = 0; q < 8; q++) sum += ts[(q * 32 + kt) * 8 + b];
            atomicAdd(&g_acc[b * D + row0 + s * SK + kt], sum);
        }
        stg ^= 1;
    }

    // ---- F reduction over 4 kg-groups + atomic flush ----------------------
    __syncthreads();
    float2* fs = (float2*)(smem + OFF_W0);      // 32KB stage, buffers now free
#pragma unroll
    for (int b = 0; b < 8; b++) {
#pragma unroll
        for (int h = 0; h < 2; h++)
            fs[(b * 2 + h) * 256 + t] = *reinterpret_cast<float2*>(&accF[b][h]);
    }
    __syncthreads();
#pragma unroll
    for (int p = 0; p < 4; p++) {
        int O  = t * 4 + p;                     // 0..1023
        int pp = O & 15;
        int jj = O >> 4;                        // j4 group 0..63
        float2 sum = make_float2(0.0f, 0.0f);
#pragma unroll
        for (int g = 0; g < 4; g++) {
            float2 v = fs[pp * 256 + g * 64 + jj];
            sum.x += v.x; sum.y += v.y;
        }
        int b = pp >> 1, h = pp & 1;
        int col = col0 + jj * 4 + h * 2;
        atomicAdd(&g_acc[b * D + col    ], sum.x);
        atomicAdd(&g_acc[b * D + col + 1], sum.y);
    }
}

// ---------------------------------------------------------------------------
// Kernel 3: epilogue  out = (acc + bias + [Ux|0]) * rho'(s)
// ---------------------------------------------------------------------------
__global__ void epi_kernel(const float* __restrict__ Ux,
                           const float* __restrict__ s,
                           const float* __restrict__ bias,
                           float* __restrict__ out) {
    int idx = blockIdx.x * blockDim.x + threadIdx.x;
    if (idx >= BATCH * D) return;
    int b = idx >> 14;
    int j = idx & (D - 1);
    float r  = sigmoid4(s[idx]);
    float rd = 4.0f * r * (1.0f - r);
    float v  = g_acc[idx] + bias[j];
    if (j < H0) v += Ux[b * H0 + j];
    out[idx] = v * rd;
}

// ---------------------------------------------------------------------------
extern "C" void kernel_launch(void* const* d_in, const int* in_sizes, int n_in,
                              void* d_out, int out_size) {
    const float *Ux = nullptr, *s = nullptr, *W = nullptr, *bias = nullptr;
    for (int i = 0; i < n_in; i++) {
        switch (in_sizes[i]) {
            case 32768:     Ux   = (const float*)d_in[i]; break;
            case 131072:    s    = (const float*)d_in[i]; break;
            case 268435456: W    = (const float*)d_in[i]; break;
            case 16384:     bias = (const float*)d_in[i]; break;
            default: break;
        }
    }

    cudaFuncSetAttribute(mm_kernel, cudaFuncAttributeMaxDynamicSharedMemorySize,
                         SMEM_TOTAL);

    prep_kernel<<<512, 256>>>(s);
    mm_kernel<<<768, THREADS, SMEM_TOTAL>>>(W);
    epi_kernel<<<(BATCH * D + 255) / 256, 256>>>(Ux, s, bias, (float*)d_out);
}